// round 17
// baseline (speedup 1.0000x reference)
#include <cuda_runtime.h>

#define CHUNK  128
#define MAXW   79
#define MAXN   (MAXW * CHUNK)   // 10112
#define MAXP   1000
#define SB     4096

typedef unsigned long long u64;

// ---- static device scratch (no allocations allowed) ----
__device__ float4     g_sboxes[MAXN];   // boxes in sorted order (pad rows stay 0)
__device__ float      g_sscores[MAXN];  // scores in sorted order
__device__ ulonglong2 g_pub[MAXW];      // published keep words per chunk
__device__ int        g_prefix[MAXW];   // rank base per chunk
__device__ volatile int g_tot[MAXW];    // 0 = unpublished, else total_kept+1
__device__ volatile int g_stopat;       // first chunk at/after MAXP reached
__device__ int        g_base[SB];       // bucket base (descending)
__device__ int        g_members[MAXN];  // indices grouped by bucket

__device__ __forceinline__ int bucket_of(float s) {
    int b = (int)(s * 4096.0f);           // monotone for s >= 0
    return max(0, min(SB - 1, b));
}

// ---------------------------------------------------------------------------
// S1: fused single-block sort front-end + chain-state reset for this replay.
// ---------------------------------------------------------------------------
__global__ void k_sortA(const float* __restrict__ scores, int N) {
    __shared__ int s_cnt[SB];
    __shared__ int s_base[SB];
    __shared__ int wsum[32];
    int tid = threadIdx.x, lane = tid & 31, wid = tid >> 5;

    // reset chain state (k_chain runs later in the same stream)
    if (tid < MAXW) g_tot[tid] = 0;
    if (tid == 0) g_stopat = 0x7fffffff;

    for (int b = tid; b < SB; b += 1024) s_cnt[b] = 0;
    __syncthreads();
    for (int i = tid; i < N; i += 1024)
        atomicAdd(&s_cnt[bucket_of(scores[i])], 1);
    __syncthreads();

    int cbase = 0;
    for (int k = 0; k < SB / 1024; k++) {
        int b = SB - 1 - (k * 1024 + tid);   // descending bucket order
        int v = s_cnt[b];
        int x = v;
        #pragma unroll
        for (int o = 1; o < 32; o <<= 1) {
            int y = __shfl_up_sync(~0u, x, o);
            if (lane >= o) x += y;
        }
        if (lane == 31) wsum[wid] = x;
        __syncthreads();
        if (wid == 0) {
            int s = wsum[lane];
            #pragma unroll
            for (int o = 1; o < 32; o <<= 1) {
                int y = __shfl_up_sync(~0u, s, o);
                if (lane >= o) s += y;
            }
            wsum[lane] = s;
        }
        __syncthreads();
        s_base[b] = cbase + (x - v) + (wid ? wsum[wid - 1] : 0);
        cbase += wsum[31];
        __syncthreads();
    }

    for (int b = tid; b < SB; b += 1024) { s_cnt[b] = 0; g_base[b] = s_base[b]; }
    __syncthreads();
    for (int i = tid; i < N; i += 1024) {
        int b = bucket_of(scores[i]);
        int slot = s_base[b] + atomicAdd(&s_cnt[b], 1);
        g_members[slot] = i;
    }
}

// ---------------------------------------------------------------------------
// S2: exact stable rank within bucket + scatter (grid-parallel).
// ---------------------------------------------------------------------------
__global__ void k_place(const float4* __restrict__ boxes,
                        const float* __restrict__ scores, int N) {
    int i = blockIdx.x * blockDim.x + threadIdx.x;
    if (i >= N) return;
    float si = scores[i];
    int b = bucket_of(si);
    int base = g_base[b];
    int cb   = ((b > 0) ? g_base[b - 1] : N) - base;
    int r = base;
    for (int t = 0; t < cb; t++) {
        int j = g_members[base + t];
        if (j == i) continue;
        float sj = scores[j];
        r += (sj > si) || (sj == si && j < i);
    }
    g_sboxes[r]  = boxes[i];
    g_sscores[r] = si;
}

// ---------------------------------------------------------------------------
// suppression test: IoU > 0.5  <=>  3*inter > areaA + areaB  (division-free)
// ---------------------------------------------------------------------------
__device__ __forceinline__ bool sup_test(float4 a, float areaA, float4 b) {
    float ix1 = fmaxf(a.x, b.x), iy1 = fmaxf(a.y, b.y);
    float ix2 = fminf(a.z, b.z), iy2 = fminf(a.w, b.w);
    float inter = fmaxf(ix2 - ix1, 0.0f) * fmaxf(iy2 - iy1, 0.0f);
    float areaB = (b.z - b.x) * (b.w - b.y);
    return 3.0f * inter > areaA + areaB;
}

// ---------------------------------------------------------------------------
// phase A (optimistic batch) over a 128-chunk; pending given directly.
// ---------------------------------------------------------------------------
__device__ __forceinline__ int phaseA_p(const ulonglong2* d, u64 P0, u64 P1,
                                        u64& k0o, u64& k1o) {
    u64 c0 = 0ull, c1 = 0ull, sup0 = 0ull, sup1 = 0ull;
    while (P0 | P1) {
        u64 o0 = 0ull, o1 = 0ull;
        u64 t = P0;
        while (t) {
            int i = __ffsll((long long)t) - 1; t &= t - 1ull;
            ulonglong2 dd = d[i]; o0 |= dd.x; o1 |= dd.y;
        }
        t = P1;
        while (t) {
            int i = __ffsll((long long)t) - 1; t &= t - 1ull;
            ulonglong2 dd = d[64 + i]; o0 |= dd.x; o1 |= dd.y;
        }
        u64 x0 = (sup0 | o0) & P0, x1 = (sup1 | o1) & P1;
        if (!(x0 | x1)) { c0 |= P0; c1 |= P1; break; }   // happy path

        int f = x0 ? (__ffsll((long long)x0) - 1)
                   : (64 + __ffsll((long long)x1) - 1);
        u64 m0, m1;                    // bits strictly below f
        if (f < 64) { m0 = (1ull << f) - 1ull; m1 = 0ull; }
        else        { m0 = ~0ull;             m1 = (1ull << (f - 64)) - 1ull; }
        u64 nc0 = P0 & m0, nc1 = P1 & m1;     // newly confirmed kept
        c0 |= nc0; c1 |= nc1;
        t = nc0;
        while (t) {
            int i = __ffsll((long long)t) - 1; t &= t - 1ull;
            ulonglong2 dd = d[i]; sup0 |= dd.x; sup1 |= dd.y;
        }
        t = nc1;
        while (t) {
            int i = __ffsll((long long)t) - 1; t &= t - 1ull;
            ulonglong2 dd = d[64 + i]; sup0 |= dd.x; sup1 |= dd.y;
        }
        P0 = P0 & ~m0 & ~sup0;
        P1 = P1 & ~m1 & ~sup1;
        if (f < 64) P0 &= ~(1ull << f); else P1 &= ~(1ull << (f - 64));
    }
    k0o = c0; k1o = c1;
    return __popcll(c0) + __popcll(c1);
}

// ---------------------------------------------------------------------------
// K3: mask-free wavefront chain. Block c owns chunk c; thread t owns box
// c*128+t. Prologue: stage own boxes in smem, compute own diag tile (smem).
// Hop d (< c): poll g_tot[d] (1 word, carries total+1); fence; read 16B keep
// word; each thread computes IoUs vs chunk d's kept boxes ON THE FLY
// (warp-broadcast L1 loads) and ORs into its private suppressed flag.
// Own turn: warp ballots -> pending word; thread 0: optimistic phase A
// (smem diag); publish {keep,prefix}; fence; g_tot[c]=total+1.
// Early-MAXP exit broadcast via g_stopat.
// ---------------------------------------------------------------------------
__global__ void __launch_bounds__(CHUNK, 1) k_chain(int N, int W) {
    __shared__ float4     sbox[CHUNK];
    __shared__ ulonglong2 sdiag[CHUNK];
    __shared__ u64 s_kx, s_ky;
    __shared__ int s_info;              // -1 = exit, else prev_total
    __shared__ unsigned sbal[4];
    int c = blockIdx.x, t = threadIdx.x;
    int lane = t & 31, wid = t >> 5;

    int g = c * CHUNK + t;
    float4 mybox = (g < N) ? g_sboxes[g] : make_float4(0.f, 0.f, 0.f, 0.f);
    float myarea = (mybox.z - mybox.x) * (mybox.w - mybox.y);
    sbox[t] = mybox;
    __syncthreads();

    // own diag row: bits j > t that box t suppresses (within own chunk)
    {
        u64 m0 = 0ull, m1 = 0ull;
        for (int j = t + 1; j < CHUNK; j++) {
            if (sup_test(mybox, myarea, sbox[j])) {
                if (j < 64) m0 |= 1ull << j; else m1 |= 1ull << (j - 64);
            }
        }
        sdiag[t] = make_ulonglong2(m0, m1);
    }
    __syncthreads();

    bool suppressed = false;
    int prev_total = 0;

    for (int d = 0; d < c; d++) {
        if (t == 0) {
            int raw;
            int e = 0;
            while ((raw = g_tot[d]) == 0) {
                if (g_stopat <= c) { e = 1; break; }
            }
            if (!e) {
                __threadfence();       // order flag read before data read
                volatile u64* pp = (volatile u64*)&g_pub[d];
                s_kx = pp[0];
                s_ky = pp[1];
                prev_total = raw - 1;
                if (prev_total >= MAXP) {
                    atomicMin((int*)&g_stopat, c);
                    e = 1;
                }
            }
            s_info = e ? -1 : prev_total;
        }
        __syncthreads();
        if (s_info < 0) {
            if (t == 0) {
                g_pub[c] = make_ulonglong2(0ull, 0ull);
                g_prefix[c] = 0;
                __threadfence();
                g_tot[c] = MAXP + 1;   // >= MAXP: downstream stops too
            }
            return;
        }
        u64 kk0 = s_kx, kk1 = s_ky;
        __syncthreads();               // protect s_kx/s_ky for next hop

        // on-the-fly suppression vs chunk d's kept boxes (4-batched ILP)
        const float4* dbox = g_sboxes + d * CHUNK;
        while (kk0 | kk1) {
            int   id[4];
            float4 bb[4];
            #pragma unroll
            for (int u = 0; u < 4; u++) {
                int i = -1;
                if (kk0)      { i = __ffsll((long long)kk0) - 1; kk0 &= kk0 - 1ull; }
                else if (kk1) { i = 64 + __ffsll((long long)kk1) - 1; kk1 &= kk1 - 1ull; }
                id[u] = i;
                bb[u] = (i >= 0) ? dbox[i] : make_float4(0.f, 0.f, 0.f, 0.f);
            }
            #pragma unroll
            for (int u = 0; u < 4; u++)
                if (id[u] >= 0) suppressed |= sup_test(mybox, myarea, bb[u]);
        }
    }

    // own turn: rebuild pending word via ballots, resolve, publish
    bool pend = !suppressed && (g < N);
    unsigned bal = __ballot_sync(0xffffffffu, pend);
    if (lane == 0) sbal[wid] = bal;
    __syncthreads();
    if (t == 0) {
        u64 p0 = (u64)sbal[0] | ((u64)sbal[1] << 32);
        u64 p1 = (u64)sbal[2] | ((u64)sbal[3] << 32);
        u64 k0, k1;
        int n = phaseA_p(sdiag, p0, p1, k0, k1);
        g_pub[c] = make_ulonglong2(k0, k1);
        g_prefix[c] = prev_total;
        __threadfence();
        g_tot[c] = prev_total + n + 1;
    }
}

// ---------------------------------------------------------------------------
// K4: apply MAX_PROPOSALS cutoff and emit outputs:
//   out[0 : 4N) boxes | out[4N : 5N) scores | out[5N : 6N) keep as 0/1
// ---------------------------------------------------------------------------
__global__ void k_out(float* __restrict__ out, int N) {
    int p = blockIdx.x * blockDim.x + threadIdx.x;
    if (p >= N) return;
    int c = p >> 7, i = p & 127;
    ulonglong2 kw = g_pub[c];
    bool kept;
    int below;
    if (i < 64) {
        kept  = (kw.x >> i) & 1ull;
        below = __popcll(kw.x & ((1ull << i) - 1ull));
    } else {
        int ii = i - 64;
        kept  = (kw.y >> ii) & 1ull;
        below = __popcll(kw.x) + __popcll(kw.y & ((1ull << ii) - 1ull));
    }
    int r = g_prefix[c] + below;
    bool fin = kept && (r < MAXP);

    float4 b = fin ? g_sboxes[p] : make_float4(0.f, 0.f, 0.f, 0.f);
    ((float4*)out)[p] = b;
    out[4 * N + p] = fin ? g_sscores[p] : 0.0f;
    out[5 * N + p] = fin ? 1.0f : 0.0f;
}

// ---------------------------------------------------------------------------
extern "C" void kernel_launch(void* const* d_in, const int* in_sizes, int n_in,
                              void* d_out, int out_size) {
    const float4* boxes  = (const float4*)d_in[0];
    const float*  scores = (const float*)d_in[1];
    int N = in_sizes[1];
    int W = (N + CHUNK - 1) / CHUNK;

    k_sortA<<<1, 1024>>>(scores, N);
    k_place<<<(N + 255) / 256, 256>>>(boxes, scores, N);
    k_chain<<<W, CHUNK>>>(N, W);
    k_out<<<(N + 255) / 256, 256>>>((float*)d_out, N);
}